// round 12
// baseline (speedup 1.0000x reference)
#include <cuda_runtime.h>
#include <cstdint>
#include <cub/cub.cuh>

#define VN_    50000
#define FN_    100000
#define S3_    (3*FN_)
#define EMAX_  S3_
#define HID_   256
#define NFMAX_ (4*FN_)
#define PEMAX_ ((S3_/5)+64)
#define NEM_   (VN_ + PEMAX_ + 3*NFMAX_)
#define SF_    (S3_ + 8*FN_)          // combined sel+flag8 scan length
#define TPB    256
#define GS3    ((S3_ + TPB - 1)/TPB)  // 1172
#define GF     ((FN_ + TPB - 1)/TPB)
#define GNE    ((NEM_ + TPB - 1)/TPB)
#define GNF3   ((3*NFMAX_ + TPB - 1)/TPB)
#define NCHS   GS3
#define NBUCK  65536

// ---------------- static device scratch (no allocation allowed) ----------------
__device__ unsigned g_sk_in[S3_];                  // biased key per slot
__device__ unsigned g_sk_out[S3_], g_sv_out[S3_];  // sorted keys + slots
__device__ unsigned long long g_pk[S3_];           // bucket-scattered (key<<19)|slot
__device__ int g_bh[NBUCK];                        // bucket counts (kB re-zeros)
__device__ int g_boff[NBUCK+1], g_bcur[NBUCK];     // bucket offsets / scatter cursors
__device__ int g_rank[S3_], g_inv[S3_];
__device__ int g_chU[NCHS], g_offU[NCHS];
__device__ int g_runstart[EMAX_+1];
__device__ int g_en0[EMAX_], g_en1[EMAX_];
__device__ float g_xe[EMAX_*4];      // padded to 4 floats/edge for vector loads
__device__ float g_rq[EMAX_*4];      // r0,r1,q0,q1 per edge (float4)
__device__ float g_y[EMAX_];
__device__ unsigned g_yk[S3_];       // 30-bit selection keys (~float_bits(y))
__device__ int g_selflag[SF_];       // [0,S3_): sel ; [S3_,S3_+8FN): flag8
__device__ int g_scan[SF_];          // exclusive scan of g_selflag
__device__ int g_nf[3*NFMAX_];
__device__ int g_histK[1024];        // key-select histogram (picks re-zero)
__device__ int g_histI[1024];        // index-select histogram (picks re-zero)
__device__ unsigned g_T;             // threshold key (30-bit)
__device__ int g_RK;                 // remaining count within key threshold
__device__ unsigned g_I;             // tie threshold index I* (19-bit)
__device__ int g_RI;
__device__ unsigned g_done = 0;      // last-block-done counter (self-resets)
__device__ int g_E, g_num;
__device__ unsigned char g_temp[48u<<20];

// ---------------- threefry2x32, key = (0,42), JAX-exact ----------------
__device__ __forceinline__ unsigned rotl32(unsigned v, int d) {
    return (v << d) | (v >> (32 - d));
}
__device__ __forceinline__ void threefry_0_42(unsigned x0, unsigned x1,
                                              unsigned& o0, unsigned& o1) {
    const unsigned k0 = 0u, k1 = 42u;
    const unsigned ks2 = k0 ^ k1 ^ 0x1BD11BDAu;
    x0 += k0; x1 += k1;
#define TF4(a,b,c,d) \
    x0 += x1; x1 = rotl32(x1,a); x1 ^= x0; \
    x0 += x1; x1 = rotl32(x1,b); x1 ^= x0; \
    x0 += x1; x1 = rotl32(x1,c); x1 ^= x0; \
    x0 += x1; x1 = rotl32(x1,d); x1 ^= x0;
    TF4(13,15,26,6);   x0 += k1;  x1 += ks2 + 1u;
    TF4(17,29,16,24);  x0 += ks2; x1 += k0  + 2u;
    TF4(13,15,26,6);   x0 += k0;  x1 += k1  + 3u;
    TF4(17,29,16,24);  x0 += k1;  x1 += ks2 + 4u;
    TF4(13,15,26,6);   x0 += ks2; x1 += k0  + 5u;
#undef TF4
    o0 = x0; o1 = x1;
}
// Partitionable-threefry (JAX >= 0.5 default): bits[i] = xor(threefry((0,42),(0,i)))
__device__ __forceinline__ unsigned tf_bits_part(unsigned i) {
    unsigned o0, o1;
    threefry_0_42(0u, i, o0, o1);
    return o0 ^ o1;
}

// exclusive in-block binary prefix over 256 threads; also returns block total
__device__ __forceinline__ int blk_prefix(int flag, int* wsum, int* total) {
    unsigned m = __ballot_sync(0xFFFFFFFFu, flag != 0);
    int lane = threadIdx.x & 31, w = threadIdx.x >> 5;
    int excl = __popc(m & ((1u << lane) - 1u));
    if (lane == 0) wsum[w] = __popc(m);
    __syncthreads();
    int off = 0, tot = 0;
    #pragma unroll
    for (int j = 0; j < 8; j++) { int v = wsum[j]; tot += v; if (j < w) off += v; }
    *total = tot;
    __syncthreads();
    return excl + off;
}

// derived category counts from the combined scan
__device__ __forceinline__ void cat_counts(int& T0, int& C1, int& C2, int& T7) {
    int num = g_num;
    int P1 = g_scan[S3_ +   FN_] - num;
    int P4 = g_scan[S3_ + 4*FN_] - num;
    int P7 = g_scan[S3_ + 7*FN_] - num;
    T0 = P1; C1 = P4 - P1; C2 = P7 - P4; T7 = FN_ - P7;
}
__device__ __forceinline__ int nf_total() {
    int T0, C1, C2, T7; cat_counts(T0, C1, C2, T7);
    return T0 + 2*C1 + 3*C2 + 4*T7;
}

// ---------------- custom stable sort (bucket by top-16 bits + in-place bucket sort) --
// kA: biased keys + global bucket histogram
__global__ void kA_keys_hist(const int* __restrict__ face) {
    int i = blockIdx.x * blockDim.x + threadIdx.x;
    if (i >= S3_) return;
    int blk = i / FN_, fc = i - blk * FN_;
    int a, b;
    if (blk == 0)      { a = face[fc*3+0]; b = face[fc*3+1]; }
    else if (blk == 1) { a = face[fc*3+1]; b = face[fc*3+2]; }
    else               { a = face[fc*3+2]; b = face[fc*3+0]; }
    int lo = min(a, b), hi = max(a, b);
    int key = (int)((unsigned)lo * (unsigned)VN_ + (unsigned)hi); // int32 wrap like JAX
    unsigned bkey = (unsigned)key ^ 0x80000000u;   // signed order -> unsigned order
    g_sk_in[i] = bkey;
    atomicAdd(&g_bh[bkey >> 16], 1);
}

// kB: 1 block / 256 threads, 256 buckets per thread; loop-based (no local arrays).
// Sets offsets + cursors, re-zeros counts (replay-safe).
__global__ void kB_scan() {
    __shared__ int part[256];
    int t = threadIdx.x;
    int base = t * 256;
    int sum = 0;
    for (int j = 0; j < 256; j++) sum += g_bh[base + j];
    part[t] = sum;
    __syncthreads();
    for (int d = 1; d < 256; d <<= 1) {
        int v = (t >= d) ? part[t-d] : 0;
        __syncthreads();
        part[t] += v;
        __syncthreads();
    }
    int run = t ? part[t-1] : 0;
    for (int j = 0; j < 256; j++) {
        int c = g_bh[base + j];
        g_bh[base + j] = 0;
        g_boff[base + j] = run;
        g_bcur[base + j] = run;
        run += c;
    }
    if (t == 255) g_boff[NBUCK] = run;   // == S3_
}

// kC: scatter (bkey<<19 | slot) into its bucket (in-bucket order arbitrary; kD sorts)
__global__ void kC_scatter() {
    int i = blockIdx.x * blockDim.x + threadIdx.x;
    if (i >= S3_) return;
    unsigned bkey = g_sk_in[i];
    int pos = atomicAdd(&g_bcur[bkey >> 16], 1);
    if (pos < 0 || pos >= S3_) return;   // defensive (cannot trigger with correct offsets)
    g_pk[pos] = (((unsigned long long)bkey) << 19) | (unsigned)i;
}

// kD: one thread per bucket; IN-PLACE insertion sort in g_pk[s,t) by 51-bit
// (bkey,slot) => exactly the stable ascending key sort. No local arrays.
__global__ void kD_bsort() {
    int b = blockIdx.x * blockDim.x + threadIdx.x;
    if (b >= NBUCK) return;
    int s = g_boff[b], t = g_boff[b+1];
    if (s < 0) s = 0;
    if (t > S3_) t = S3_;
    if (t - s <= 0) return;
    for (int j = s + 1; j < t; j++) {
        unsigned long long v = g_pk[j];
        int p = j - 1;
        while (p >= s && g_pk[p] > v) { g_pk[p+1] = g_pk[p]; p--; }
        g_pk[p+1] = v;
    }
    for (int j = s; j < t; j++) {
        unsigned long long v = g_pk[j];
        g_sk_out[j] = (unsigned)(v >> 19);
        g_sv_out[j] = (unsigned)(v & 0x7FFFFull);
    }
}

// ---------------- downstream pipeline (byte-identical to passing R10) ----------------
__global__ void k_head() {
    __shared__ int wsum[8];
    int i = blockIdx.x * blockDim.x + threadIdx.x;
    int flag = (i < S3_) && (i == 0 || g_sk_out[i] != g_sk_out[i-1]);
    int tot;
    int excl = blk_prefix(flag, wsum, &tot);
    if (i < S3_) g_rank[i] = excl + flag;   // in-chunk inclusive
    if (threadIdx.x == 0) g_chU[blockIdx.x] = tot;
}

__global__ void k_tiny1() {
    __shared__ int part[1024];
    int t = threadIdx.x;
    int a0 = (2*t   < NCHS) ? g_chU[2*t]   : 0;
    int a1 = (2*t+1 < NCHS) ? g_chU[2*t+1] : 0;
    part[t] = a0 + a1;
    __syncthreads();
    for (int d = 1; d < 1024; d <<= 1) {
        int v = (t >= d) ? part[t-d] : 0;
        __syncthreads();
        part[t] += v;
        __syncthreads();
    }
    int base = t ? part[t-1] : 0;
    if (2*t   < NCHS) g_offU[2*t]   = base;
    if (2*t+1 < NCHS) g_offU[2*t+1] = base + a0;
}

__global__ void k_unique(const float* __restrict__ x, const int* __restrict__ divp) {
    int i = blockIdx.x * blockDim.x + threadIdx.x;
    if (i >= S3_) return;
    int r = g_offU[blockIdx.x] + g_rank[i];   // global inclusive rank
    int flag = (i == 0 || g_sk_out[i] != g_sk_out[i-1]);
    if (flag) {
        int e = r - 1;
        g_runstart[e] = i;
        int k = (int)(g_sk_out[i] ^ 0x80000000u);
        int q = k / VN_, rm = k % VN_;     // C trunc -> numpy floor fixup
        if (rm < 0) { rm += VN_; q -= 1; }
        g_en0[e] = q; g_en1[e] = rm;
        int i0 = (q < 0) ? q + VN_ : q;    // JAX gather: negative wrap, then clamp
        if (i0 < 0) i0 = 0;
        if (i0 >= VN_) i0 = VN_ - 1;
        float4 v;
        v.x = 0.5f * (x[i0*3+0] + x[rm*3+0]);
        v.y = 0.5f * (x[i0*3+1] + x[rm*3+1]);
        v.z = 0.5f * (x[i0*3+2] + x[rm*3+2]);
        v.w = 0.f;
        *(float4*)&g_xe[e*4] = v;
    }
    g_inv[g_sv_out[i]] = r - 1;
    if (i == S3_ - 1) { g_E = r; g_runstart[r] = S3_; g_num = r / divp[0]; }
}

__global__ void k_gnn1(const float* __restrict__ W1s, const float* __restrict__ W1n,
                       const float* __restrict__ b1,  const float* __restrict__ W2s,
                       const float* __restrict__ W2n) {
    __shared__ float s1s[3*HID_], s1n[3*HID_], sb[HID_], s2s[2*HID_], s2n[2*HID_];
    for (int i = threadIdx.x; i < 3*HID_; i += blockDim.x) { s1s[i] = W1s[i]; s1n[i] = W1n[i]; }
    for (int i = threadIdx.x; i < HID_;   i += blockDim.x) {
        sb[i] = b1[i];
        s2s[i] = W2s[i*2+0]; s2s[HID_+i] = W2s[i*2+1];
        s2n[i] = W2n[i*2+0]; s2n[HID_+i] = W2n[i*2+1];
    }
    __syncthreads();
    int e = blockIdx.x * blockDim.x + threadIdx.x;
    if (e >= EMAX_ || e >= g_E) return;
    int s = g_runstart[e], t = g_runstart[e+1];
    float deg = (float)(2*(t-s) + 1);
    float4 xev = *(const float4*)&g_xe[e*4];
    float xe0 = xev.x, xe1 = xev.y, xe2 = xev.z;
    float ax0 = xe0, ax1 = xe1, ax2 = xe2;   // self loop
    for (int i = s; i < t; i++) {
        int slot = (int)g_sv_out[i];
        int fc = slot % FN_, j = slot / FN_;
        int e1 = g_inv[((j+1)%3)*FN_ + fc];
        int e2 = g_inv[((j+2)%3)*FN_ + fc];
        float4 v1 = *(const float4*)&g_xe[e1*4];
        float4 v2 = *(const float4*)&g_xe[e2*4];
        ax0 += v1.x + v2.x;
        ax1 += v1.y + v2.y;
        ax2 += v1.z + v2.z;
    }
    ax0 /= deg; ax1 /= deg; ax2 /= deg;
    float r0 = 0.f, r1 = 0.f, q0 = 0.f, q1 = 0.f;
    for (int k4 = 0; k4 < HID_; k4 += 4) {
        float4 vb  = *(const float4*)&sb[k4];
        float4 a0v = *(const float4*)&s1s[k4];
        float4 a1v = *(const float4*)&s1s[HID_ + k4];
        float4 a2v = *(const float4*)&s1s[2*HID_ + k4];
        float4 n0v = *(const float4*)&s1n[k4];
        float4 n1v = *(const float4*)&s1n[HID_ + k4];
        float4 n2v = *(const float4*)&s1n[2*HID_ + k4];
        float4 w0v = *(const float4*)&s2s[k4];
        float4 w1v = *(const float4*)&s2s[HID_ + k4];
        float4 u0v = *(const float4*)&s2n[k4];
        float4 u1v = *(const float4*)&s2n[HID_ + k4];
        #define GNN_STEP(c) { \
            float pre = vb.c + xe0*a0v.c + xe1*a1v.c + xe2*a2v.c \
                             + ax0*n0v.c + ax1*n1v.c + ax2*n2v.c; \
            float h = fmaxf(pre, 0.f); \
            r0 += h * w0v.c;  r1 += h * w1v.c; \
            q0 += h * u0v.c;  q1 += h * u1v.c; }
        GNN_STEP(x) GNN_STEP(y) GNN_STEP(z) GNN_STEP(w)
        #undef GNN_STEP
    }
    float4 outv; outv.x = r0; outv.y = r1; outv.z = q0; outv.w = q1;
    *(float4*)&g_rq[e*4] = outv;
}

__global__ void k_gumbel(const float* __restrict__ b2) {
    int e = blockIdx.x * blockDim.x + threadIdx.x;
    if (e >= S3_) return;
    int E = g_E;
    if (e >= E) { g_yk[e] = 0xFFFFFFFFu; return; }
    int s = g_runstart[e], t = g_runstart[e+1];
    float deg = (float)(2*(t-s) + 1);
    float4 rqv = *(const float4*)&g_rq[e*4];
    float aq0 = rqv.z, aq1 = rqv.w;              // self loop
    for (int i = s; i < t; i++) {
        int slot = (int)g_sv_out[i];
        int fc = slot % FN_, j = slot / FN_;
        int e1 = g_inv[((j+1)%3)*FN_ + fc];
        int e2 = g_inv[((j+2)%3)*FN_ + fc];
        float4 v1 = *(const float4*)&g_rq[e1*4];
        float4 v2 = *(const float4*)&g_rq[e2*4];
        aq0 += v1.z + v2.z;
        aq1 += v1.w + v2.w;
    }
    float o0 = rqv.x + aq0/deg + b2[0];
    float o1 = rqv.y + aq1/deg + b2[1];
    float l0 = 1.f / (1.f + expf(-o0));           // sigmoid logits
    float l1 = 1.f / (1.f + expf(-o1));
    unsigned bb0 = tf_bits_part(2u*(unsigned)e);
    unsigned bb1 = tf_bits_part(2u*(unsigned)e + 1u);
    float U0 = __uint_as_float((bb0 >> 9) | 0x3F800000u) - 1.0f;
    float U1 = __uint_as_float((bb1 >> 9) | 0x3F800000u) - 1.0f;
    float gg0 = -logf(-logf(U0 + 1e-20f) + 1e-20f);
    float gg1 = -logf(-logf(U1 + 1e-20f) + 1e-20f);
    float z0 = (l0 + gg0) / 0.1f, z1 = (l1 + gg1) / 0.1f;
    float m  = fmaxf(z0, z1);
    float ez0 = expf(z0 - m), ez1 = expf(z1 - m);
    float y = ez0 / (ez0 + ez1);
    g_y[e] = y;
    g_yk[e] = (~__float_as_uint(y)) & 0x3FFFFFFFu;  // smaller key == larger y
}

// pick: find k-th crossing over nb buckets, update state, re-zero hist.
__device__ void dev_pick(int* hist, int nb, int shift, int kind) {
    __shared__ int sc[256];
    int t = threadIdx.x;
    int per = nb >> 8;
    int base = t * per;
    int vals[4];
    int local = 0;
    for (int j = 0; j < per; j++) { vals[j] = hist[base+j]; hist[base+j] = 0; local += vals[j]; }
    sc[t] = local;
    __syncthreads();
    for (int d = 1; d < 256; d <<= 1) {
        int v = (t >= d) ? sc[t-d] : 0;
        __syncthreads();
        sc[t] += v;
        __syncthreads();
    }
    int k = (kind == 0) ? g_num : (kind == 3) ? g_RI : g_RK;
    int cumex = sc[t] - local;
    if (cumex < k && sc[t] >= k) {
        int c = cumex;
        for (int j = 0; j < per; j++) {
            if (c + vals[j] >= k) {
                unsigned b = (unsigned)(base + j);
                int rem = k - c;
                if (kind == 0)      { g_T = b << shift; g_RK = rem; }
                else if (kind == 1) { g_T |= b << shift; g_RK = rem; }
                else if (kind == 2) { g_I = b << shift; g_RI = rem; }
                else                { g_I |= b << shift; }
                break;
            }
            c += vals[j];
        }
    }
}

// hist level + inline pick by the LAST finished block
__global__ void k_histpick(int shift, int matchshift, int bmask, int kind,
                           int idxlevel, int* hist) {
    __shared__ int sh[1024];
    __shared__ int slast;
    for (int j = threadIdx.x; j < 1024; j += 256) sh[j] = 0;
    __syncthreads();
    int E = g_E;
    unsigned T = g_T, I = g_I;
    int i = blockIdx.x * 256 + threadIdx.x;
    if (i < E) {
        unsigned key = g_yk[i];
        if (!idxlevel) {
            if ((key >> matchshift) == (T >> matchshift))
                atomicAdd(&sh[(key >> shift) & bmask], 1);
        } else {
            if (key == T && (((unsigned)i) >> matchshift) == (I >> matchshift))
                atomicAdd(&sh[(((unsigned)i) >> shift) & bmask], 1);
        }
    }
    __syncthreads();
    for (int j = threadIdx.x; j < 1024; j += 256)
        if (sh[j]) atomicAdd(&hist[j], sh[j]);
    __threadfence();
    if (threadIdx.x == 0) {
        unsigned d = atomicAdd(&g_done, 1u);
        slast = (d == gridDim.x - 1) ? 1 : 0;
    }
    __syncthreads();
    if (slast) {
        if (threadIdx.x == 0) g_done = 0;   // self-reset for next level / replay
        dev_pick(hist, bmask + 1, shift, kind);
    }
}

__global__ void k_sel() {
    int e = blockIdx.x * blockDim.x + threadIdx.x;
    if (e >= S3_) return;
    unsigned T = g_T, I = g_I;
    unsigned key = g_yk[e];
    g_selflag[e] = (e < g_E) && (key < T || (key == T && (unsigned)e <= I));
}

__global__ void k_cat() {
    int fc = blockIdx.x * blockDim.x + threadIdx.x;
    if (fc >= FN_) return;
    int m0 = g_selflag[g_inv[fc]];
    int m1 = g_selflag[g_inv[FN_ + fc]];
    int m2 = g_selflag[g_inv[2*FN_ + fc]];
    int pen = m0 + m1 + m2;
    int psi = m1 + 2*m2;
    int cat = (pen == 0) ? 0 : (pen == 1) ? 1 + psi : (pen == 2) ? 3 + psi : 7;
    #pragma unroll
    for (int k = 0; k < 8; k++) g_selflag[S3_ + k*FN_ + fc] = (k == cat) ? 1 : 0;
}

__device__ __forceinline__ void wtri(int row, int a, int b, int c) {
    g_nf[row*3+0] = a; g_nf[row*3+1] = b; g_nf[row*3+2] = c;
}

__global__ void k_faces(const int* __restrict__ face) {
    int fc = blockIdx.x * blockDim.x + threadIdx.x;
    if (fc >= FN_) return;
    int T0, C1, C2, T7; cat_counts(T0, C1, C2, T7);
    int num = g_num;
    int f0 = face[fc*3+0], f1 = face[fc*3+1], f2 = face[fc*3+2];
    int e0 = g_inv[fc], e1 = g_inv[FN_+fc], e2 = g_inv[2*FN_+fc];
    int m0 = g_selflag[e0], m1 = g_selflag[e1], m2 = g_selflag[e2];
    int p0 = VN_ + g_scan[e0], p1 = VN_ + g_scan[e1], p2 = VN_ + g_scan[e2];
    int pen = m0 + m1 + m2, psi = m1 + 2*m2;
    int cat = (pen == 0) ? 0 : (pen == 1) ? 1 + psi : (pen == 2) ? 3 + psi : 7;
    int pos = g_scan[S3_ + cat*FN_ + fc] - num;
    if (cat == 0) {
        wtri(pos, f0, f1, f2);
    } else if (cat <= 3) {                  // pen==1
        int g = pos - T0;
        int rA = T0 + g, rB = T0 + C1 + g;
        if (cat == 1)      { wtri(rA, f0, p0, f2); wtri(rB, p0, f1, f2); }
        else if (cat == 2) { wtri(rA, f1, p1, f0); wtri(rB, p1, f2, f0); }
        else               { wtri(rA, f2, p2, f1); wtri(rB, p2, f0, f1); }
    } else if (cat <= 6) {                  // pen==2
        int g = pos - (T0 + C1);
        int base2 = T0 + 2*C1;
        int rA = base2 + g, rB = base2 + C2 + g, rC = base2 + 2*C2 + g;
        if (cat == 4)      { wtri(rA, f0, p0, f2); wtri(rB, p0, f1, p1); wtri(rC, p0, p1, f2); }
        else if (cat == 5) { wtri(rA, f2, p2, f1); wtri(rB, p2, f0, p0); wtri(rC, p2, p0, f1); }
        else               { wtri(rA, f1, p1, f0); wtri(rB, p1, f2, p2); wtri(rC, p1, p2, f0); }
    } else {                                // pen==3
        int r = pos - (T0 + C1 + C2);
        int base3 = T0 + 2*C1 + 3*C2;
        wtri(base3 + r,        f0, p0, p2);
        wtri(base3 + T7 + r,   p0, f1, p1);
        wtri(base3 + 2*T7 + r, p0, p1, p2);
        wtri(base3 + 3*T7 + r, p1, f2, p2);
    }
}

// all three output sections in one launch (block-range dispatch)
__global__ void k_outputs(float* __restrict__ out) {
    int b = blockIdx.x;
    if (b < GS3) {
        int e = b * TPB + threadIdx.x;
        if (e >= EMAX_ || e >= g_E) return;
        int NF = nf_total();
        int NE = VN_ + g_num + 3*NF;
        int oM = 2*g_E + 3*NF + 2*NE;
        out[2*e]   = (float)g_en0[e];
        out[2*e+1] = (float)g_en1[e];
        float y  = g_y[e];
        float yh = g_selflag[e] ? 1.f : 0.f;
        out[oM + e] = (yh - y) + y;      // straight-through mask
    } else if (b < GS3 + GNF3) {
        int i = (b - GS3) * TPB + threadIdx.x;
        if (i >= 3*NFMAX_ || i >= 3*nf_total()) return;
        out[2*g_E + i] = (float)g_nf[i];
    } else {
        int t = (b - GS3 - GNF3) * TPB + threadIdx.x;
        if (t >= NEM_) return;
        int NF = nf_total();
        int NE = VN_ + g_num + 3*NF;
        if (t >= NE) return;
        int oNE = 2*g_E + 3*NF;
        int base = VN_ + g_num;
        int s, d;
        if (t < base) { s = t; d = t; }
        else {
            int u = t - base;
            if (u < NF)          { s = g_nf[u*3+0];        d = g_nf[u*3+1]; }
            else if (u < 2*NF)   { int r = u - NF;   s = g_nf[r*3+1]; d = g_nf[r*3+2]; }
            else                 { int r = u - 2*NF; s = g_nf[r*3+2]; d = g_nf[r*3+0]; }
        }
        out[oNE + t]      = (float)s;
        out[oNE + NE + t] = (float)d;
    }
}

// ---------------- host ----------------
extern "C" void kernel_launch(void* const* d_in, const int* in_sizes, int n_in,
                              void* d_out, int out_size) {
    const float* x    = (const float*)d_in[0];
    const int*   face = (const int*)d_in[1];
    const int*   divp = (const int*)d_in[4];
    const float* W1s  = (const float*)d_in[5];
    const float* W1n  = (const float*)d_in[6];
    const float* b1   = (const float*)d_in[7];
    const float* W2s  = (const float*)d_in[8];
    const float* W2n  = (const float*)d_in[9];
    const float* b2   = (const float*)d_in[10];
    float* out = (float*)d_out;

    void *tp, *pselflag, *pscan, *phistK, *phistI;
    cudaGetSymbolAddress(&tp,      g_temp);
    cudaGetSymbolAddress(&pselflag,g_selflag);
    cudaGetSymbolAddress(&pscan,   g_scan);
    cudaGetSymbolAddress(&phistK,  g_histK);
    cudaGetSymbolAddress(&phistI,  g_histI);
    cudaStream_t st = 0;
    size_t tb;

    // custom stable sort by biased key (bucket top-16 + in-place per-bucket sort)
    kA_keys_hist<<<GS3, TPB, 0, st>>>(face);
    kB_scan<<<1, 256, 0, st>>>();
    kC_scatter<<<GS3, TPB, 0, st>>>();
    kD_bsort<<<NBUCK/256, 256, 0, st>>>();

    k_head<<<GS3, TPB, 0, st>>>();
    k_tiny1<<<1, 1024, 0, st>>>();
    k_unique<<<GS3, TPB, 0, st>>>(x, divp);
    k_gnn1<<<GS3, TPB, 0, st>>>(W1s, W1n, b1, W2s, W2n);
    k_gumbel<<<GS3, TPB, 0, st>>>(b2);

    // radix-select: key 3x10 bits, tie-index 10+9 bits; pick fused into each level
    k_histpick<<<GS3, TPB, 0, st>>>(20, 30, 1023, 0, 0, (int*)phistK);
    k_histpick<<<GS3, TPB, 0, st>>>(10, 20, 1023, 1, 0, (int*)phistK);
    k_histpick<<<GS3, TPB, 0, st>>>( 0, 10, 1023, 1, 0, (int*)phistK);
    k_histpick<<<GS3, TPB, 0, st>>>( 9, 19, 1023, 2, 1, (int*)phistI);
    k_histpick<<<GS3, TPB, 0, st>>>( 0,  9,  511, 3, 1, (int*)phistI);
    k_sel<<<GS3, TPB, 0, st>>>();

    k_cat<<<GF, TPB, 0, st>>>();
    // one combined scan: sel (pool ranks) + 8-category face flags
    tb = sizeof(g_temp);
    cub::DeviceScan::ExclusiveSum(tp, tb, (const int*)pselflag, (int*)pscan, SF_, st);
    k_faces<<<GF, TPB, 0, st>>>(face);

    k_outputs<<<GS3 + GNF3 + GNE, TPB, 0, st>>>(out);
}

// round 14
// speedup vs baseline: 1.8538x; 1.8538x over previous
#include <cuda_runtime.h>
#include <cstdint>
#include <cub/cub.cuh>

#define VN_    50000
#define FN_    100000
#define S3_    (3*FN_)
#define EMAX_  S3_
#define HID_   256
#define NFMAX_ (4*FN_)
#define PEMAX_ ((S3_/5)+64)
#define NEM_   (VN_ + PEMAX_ + 3*NFMAX_)
#define TPB    256
#define GS3    ((S3_ + TPB - 1)/TPB)  // 1172
#define GF     ((FN_ + TPB - 1)/TPB)  // 391
#define GNE    ((NEM_ + TPB - 1)/TPB)
#define GNF3   ((3*NFMAX_ + TPB - 1)/TPB)
#define NCHS   GS3
#define NCHF   GF

// ---------------- static device scratch (no allocation allowed) ----------------
__device__ unsigned g_sk_in[S3_], g_sk_out[S3_], g_sv_in[S3_], g_sv_out[S3_];
__device__ int g_rank[S3_], g_inv[S3_];
__device__ int g_chU[NCHS], g_offU[NCHS];
__device__ int g_runstart[EMAX_+1];
__device__ int g_en0[EMAX_], g_en1[EMAX_];
__device__ float g_xe[EMAX_*4];      // padded to 4 floats/edge for vector loads
__device__ float g_rq[EMAX_*4];      // r0,r1,q0,q1 per edge (float4)
__device__ float g_y[EMAX_];
__device__ unsigned g_yk[S3_];       // 30-bit selection keys (~float_bits(y))
__device__ int g_selflag[S3_], g_selpre[S3_];
__device__ int g_chS[NCHS], g_offS[NCHS];
__device__ int g_catpre[FN_];
__device__ int g_chC[8*NCHF], g_offC[8*NCHF];
__device__ int g_catStart[9];
__device__ int g_nf[3*NFMAX_];
__device__ int g_histK[1024];        // key-select histogram (picks re-zero)
__device__ int g_histI[1024];        // index-select histogram (picks re-zero)
__device__ unsigned g_T;             // threshold key (30-bit)
__device__ int g_RK;                 // remaining count within key threshold
__device__ unsigned g_I;             // tie threshold index I* (19-bit)
__device__ int g_RI;
__device__ unsigned g_done = 0;      // last-block-done counter (self-resets)
__device__ int g_E, g_num;
__device__ unsigned char g_temp[48u<<20];

// ---------------- threefry2x32, key = (0,42), JAX-exact ----------------
__device__ __forceinline__ unsigned rotl32(unsigned v, int d) {
    return (v << d) | (v >> (32 - d));
}
__device__ __forceinline__ void threefry_0_42(unsigned x0, unsigned x1,
                                              unsigned& o0, unsigned& o1) {
    const unsigned k0 = 0u, k1 = 42u;
    const unsigned ks2 = k0 ^ k1 ^ 0x1BD11BDAu;
    x0 += k0; x1 += k1;
#define TF4(a,b,c,d) \
    x0 += x1; x1 = rotl32(x1,a); x1 ^= x0; \
    x0 += x1; x1 = rotl32(x1,b); x1 ^= x0; \
    x0 += x1; x1 = rotl32(x1,c); x1 ^= x0; \
    x0 += x1; x1 = rotl32(x1,d); x1 ^= x0;
    TF4(13,15,26,6);   x0 += k1;  x1 += ks2 + 1u;
    TF4(17,29,16,24);  x0 += ks2; x1 += k0  + 2u;
    TF4(13,15,26,6);   x0 += k0;  x1 += k1  + 3u;
    TF4(17,29,16,24);  x0 += k1;  x1 += ks2 + 4u;
    TF4(13,15,26,6);   x0 += ks2; x1 += k0  + 5u;
#undef TF4
    o0 = x0; o1 = x1;
}
// Partitionable-threefry (JAX >= 0.5 default): bits[i] = xor(threefry((0,42),(0,i)))
__device__ __forceinline__ unsigned tf_bits_part(unsigned i) {
    unsigned o0, o1;
    threefry_0_42(0u, i, o0, o1);
    return o0 ^ o1;
}

// exclusive in-block binary prefix over 256 threads; also returns block total
__device__ __forceinline__ int blk_prefix(int flag, int* wsum, int* total) {
    unsigned m = __ballot_sync(0xFFFFFFFFu, flag != 0);
    int lane = threadIdx.x & 31, w = threadIdx.x >> 5;
    int excl = __popc(m & ((1u << lane) - 1u));
    if (lane == 0) wsum[w] = __popc(m);
    __syncthreads();
    int off = 0, tot = 0;
    #pragma unroll
    for (int j = 0; j < 8; j++) { int v = wsum[j]; tot += v; if (j < w) off += v; }
    *total = tot;
    __syncthreads();
    return excl + off;
}

// category counts from catStart
__device__ __forceinline__ void cat_counts(int& T0, int& C1, int& C2, int& T7) {
    T0 = g_catStart[1];
    C1 = g_catStart[4] - g_catStart[1];
    C2 = g_catStart[7] - g_catStart[4];
    T7 = FN_ - g_catStart[7];
}
__device__ __forceinline__ int nf_total() {
    int T0, C1, C2, T7; cat_counts(T0, C1, C2, T7);
    return T0 + 2*C1 + 3*C2 + 4*T7;
}

// ---------------- kernels ----------------
__global__ void k_build_keys(const int* __restrict__ face) {
    int i = blockIdx.x * blockDim.x + threadIdx.x;
    if (i >= S3_) return;
    int blk = i / FN_, fc = i - blk * FN_;
    int a, b;
    if (blk == 0)      { a = face[fc*3+0]; b = face[fc*3+1]; }
    else if (blk == 1) { a = face[fc*3+1]; b = face[fc*3+2]; }
    else               { a = face[fc*3+2]; b = face[fc*3+0]; }
    int lo = min(a, b), hi = max(a, b);
    int key = (int)((unsigned)lo * (unsigned)VN_ + (unsigned)hi); // int32 wrap like JAX
    g_sk_in[i] = (unsigned)key ^ 0x80000000u;  // signed order under unsigned radix
    g_sv_in[i] = (unsigned)i;
}

// head flags + in-chunk inclusive prefix + chunk totals (proven since R9)
__global__ void k_head() {
    __shared__ int wsum[8];
    int i = blockIdx.x * blockDim.x + threadIdx.x;
    int flag = (i < S3_) && (i == 0 || g_sk_out[i] != g_sk_out[i-1]);
    int tot;
    int excl = blk_prefix(flag, wsum, &tot);
    if (i < S3_) g_rank[i] = excl + flag;   // in-chunk inclusive
    if (threadIdx.x == 0) g_chU[blockIdx.x] = tot;
}

// single-block exclusive scan of chunk totals
__global__ void k_tiny1() {
    __shared__ int part[1024];
    int t = threadIdx.x;
    int a0 = (2*t   < NCHS) ? g_chU[2*t]   : 0;
    int a1 = (2*t+1 < NCHS) ? g_chU[2*t+1] : 0;
    part[t] = a0 + a1;
    __syncthreads();
    for (int d = 1; d < 1024; d <<= 1) {
        int v = (t >= d) ? part[t-d] : 0;
        __syncthreads();
        part[t] += v;
        __syncthreads();
    }
    int base = t ? part[t-1] : 0;
    if (2*t   < NCHS) g_offU[2*t]   = base;
    if (2*t+1 < NCHS) g_offU[2*t+1] = base + a0;
}

// unique + inverse map + scalars + edge-node endpoints + xe, fused
__global__ void k_unique(const float* __restrict__ x, const int* __restrict__ divp) {
    int i = blockIdx.x * blockDim.x + threadIdx.x;
    if (i >= S3_) return;
    int r = g_offU[blockIdx.x] + g_rank[i];   // global inclusive rank
    int flag = (i == 0 || g_sk_out[i] != g_sk_out[i-1]);
    if (flag) {
        int e = r - 1;
        g_runstart[e] = i;
        int k = (int)(g_sk_out[i] ^ 0x80000000u);
        int q = k / VN_, rm = k % VN_;     // C trunc -> numpy floor fixup
        if (rm < 0) { rm += VN_; q -= 1; }
        g_en0[e] = q; g_en1[e] = rm;
        int i0 = (q < 0) ? q + VN_ : q;    // JAX gather: negative wrap, then clamp
        if (i0 < 0) i0 = 0;
        if (i0 >= VN_) i0 = VN_ - 1;
        float4 v;
        v.x = 0.5f * (x[i0*3+0] + x[rm*3+0]);
        v.y = 0.5f * (x[i0*3+1] + x[rm*3+1]);
        v.z = 0.5f * (x[i0*3+2] + x[rm*3+2]);
        v.w = 0.f;
        *(float4*)&g_xe[e*4] = v;
    }
    g_inv[g_sv_out[i]] = r - 1;
    if (i == S3_ - 1) { g_E = r; g_runstart[r] = S3_; g_num = r / divp[0]; }
}

__global__ void k_gnn1(const float* __restrict__ W1s, const float* __restrict__ W1n,
                       const float* __restrict__ b1,  const float* __restrict__ W2s,
                       const float* __restrict__ W2n) {
    __shared__ float s1s[3*HID_], s1n[3*HID_], sb[HID_], s2s[2*HID_], s2n[2*HID_];
    for (int i = threadIdx.x; i < 3*HID_; i += blockDim.x) { s1s[i] = W1s[i]; s1n[i] = W1n[i]; }
    for (int i = threadIdx.x; i < HID_;   i += blockDim.x) {
        sb[i] = b1[i];
        s2s[i] = W2s[i*2+0]; s2s[HID_+i] = W2s[i*2+1];
        s2n[i] = W2n[i*2+0]; s2n[HID_+i] = W2n[i*2+1];
    }
    __syncthreads();
    int e = blockIdx.x * blockDim.x + threadIdx.x;
    if (e >= EMAX_ || e >= g_E) return;
    int s = g_runstart[e], t = g_runstart[e+1];
    float deg = (float)(2*(t-s) + 1);
    float4 xev = *(const float4*)&g_xe[e*4];
    float xe0 = xev.x, xe1 = xev.y, xe2 = xev.z;
    float ax0 = xe0, ax1 = xe1, ax2 = xe2;   // self loop
    for (int i = s; i < t; i++) {
        int slot = (int)g_sv_out[i];
        int fc = slot % FN_, j = slot / FN_;
        int e1 = g_inv[((j+1)%3)*FN_ + fc];
        int e2 = g_inv[((j+2)%3)*FN_ + fc];
        float4 v1 = *(const float4*)&g_xe[e1*4];
        float4 v2 = *(const float4*)&g_xe[e2*4];
        ax0 += v1.x + v2.x;
        ax1 += v1.y + v2.y;
        ax2 += v1.z + v2.z;
    }
    ax0 /= deg; ax1 /= deg; ax2 /= deg;
    float r0 = 0.f, r1 = 0.f, q0 = 0.f, q1 = 0.f;
    for (int k4 = 0; k4 < HID_; k4 += 4) {
        float4 vb  = *(const float4*)&sb[k4];
        float4 a0v = *(const float4*)&s1s[k4];
        float4 a1v = *(const float4*)&s1s[HID_ + k4];
        float4 a2v = *(const float4*)&s1s[2*HID_ + k4];
        float4 n0v = *(const float4*)&s1n[k4];
        float4 n1v = *(const float4*)&s1n[HID_ + k4];
        float4 n2v = *(const float4*)&s1n[2*HID_ + k4];
        float4 w0v = *(const float4*)&s2s[k4];
        float4 w1v = *(const float4*)&s2s[HID_ + k4];
        float4 u0v = *(const float4*)&s2n[k4];
        float4 u1v = *(const float4*)&s2n[HID_ + k4];
        #define GNN_STEP(c) { \
            float pre = vb.c + xe0*a0v.c + xe1*a1v.c + xe2*a2v.c \
                             + ax0*n0v.c + ax1*n1v.c + ax2*n2v.c; \
            float h = fmaxf(pre, 0.f); \
            r0 += h * w0v.c;  r1 += h * w1v.c; \
            q0 += h * u0v.c;  q1 += h * u1v.c; }
        GNN_STEP(x) GNN_STEP(y) GNN_STEP(z) GNN_STEP(w)
        #undef GNN_STEP
    }
    float4 outv; outv.x = r0; outv.y = r1; outv.z = q0; outv.w = q1;
    *(float4*)&g_rq[e*4] = outv;
}

__global__ void k_gumbel(const float* __restrict__ b2) {
    int e = blockIdx.x * blockDim.x + threadIdx.x;
    if (e >= S3_) return;
    int E = g_E;
    if (e >= E) { g_yk[e] = 0xFFFFFFFFu; return; }
    int s = g_runstart[e], t = g_runstart[e+1];
    float deg = (float)(2*(t-s) + 1);
    float4 rqv = *(const float4*)&g_rq[e*4];
    float aq0 = rqv.z, aq1 = rqv.w;              // self loop
    for (int i = s; i < t; i++) {
        int slot = (int)g_sv_out[i];
        int fc = slot % FN_, j = slot / FN_;
        int e1 = g_inv[((j+1)%3)*FN_ + fc];
        int e2 = g_inv[((j+2)%3)*FN_ + fc];
        float4 v1 = *(const float4*)&g_rq[e1*4];
        float4 v2 = *(const float4*)&g_rq[e2*4];
        aq0 += v1.z + v2.z;
        aq1 += v1.w + v2.w;
    }
    float o0 = rqv.x + aq0/deg + b2[0];
    float o1 = rqv.y + aq1/deg + b2[1];
    float l0 = 1.f / (1.f + expf(-o0));           // sigmoid logits
    float l1 = 1.f / (1.f + expf(-o1));
    unsigned bb0 = tf_bits_part(2u*(unsigned)e);
    unsigned bb1 = tf_bits_part(2u*(unsigned)e + 1u);
    float U0 = __uint_as_float((bb0 >> 9) | 0x3F800000u) - 1.0f;
    float U1 = __uint_as_float((bb1 >> 9) | 0x3F800000u) - 1.0f;
    float gg0 = -logf(-logf(U0 + 1e-20f) + 1e-20f);
    float gg1 = -logf(-logf(U1 + 1e-20f) + 1e-20f);
    float z0 = (l0 + gg0) / 0.1f, z1 = (l1 + gg1) / 0.1f;
    float m  = fmaxf(z0, z1);
    float ez0 = expf(z0 - m), ez1 = expf(z1 - m);
    float y = ez0 / (ez0 + ez1);
    g_y[e] = y;
    g_yk[e] = (~__float_as_uint(y)) & 0x3FFFFFFFu;  // smaller key == larger y
}

// pick: find k-th crossing over nb buckets, update state, re-zero hist.
__device__ void dev_pick(int* hist, int nb, int shift, int kind) {
    __shared__ int sc[256];
    int t = threadIdx.x;
    int per = nb >> 8;
    int base = t * per;
    int vals[4];
    int local = 0;
    for (int j = 0; j < per; j++) { vals[j] = hist[base+j]; hist[base+j] = 0; local += vals[j]; }
    sc[t] = local;
    __syncthreads();
    for (int d = 1; d < 256; d <<= 1) {
        int v = (t >= d) ? sc[t-d] : 0;
        __syncthreads();
        sc[t] += v;
        __syncthreads();
    }
    int k = (kind == 0) ? g_num : (kind == 3) ? g_RI : g_RK;
    int cumex = sc[t] - local;
    if (cumex < k && sc[t] >= k) {
        int c = cumex;
        for (int j = 0; j < per; j++) {
            if (c + vals[j] >= k) {
                unsigned b = (unsigned)(base + j);
                int rem = k - c;
                if (kind == 0)      { g_T = b << shift; g_RK = rem; }
                else if (kind == 1) { g_T |= b << shift; g_RK = rem; }
                else if (kind == 2) { g_I = b << shift; g_RI = rem; }
                else                { g_I |= b << shift; }
                break;
            }
            c += vals[j];
        }
    }
}

// hist level + inline pick by the LAST finished block (launch-bounded visibility)
__global__ void k_histpick(int shift, int matchshift, int bmask, int kind,
                           int idxlevel, int* hist) {
    __shared__ int sh[1024];
    __shared__ int slast;
    for (int j = threadIdx.x; j < 1024; j += 256) sh[j] = 0;
    __syncthreads();
    int E = g_E;
    unsigned T = g_T, I = g_I;
    int i = blockIdx.x * 256 + threadIdx.x;
    if (i < E) {
        unsigned key = g_yk[i];
        if (!idxlevel) {
            if ((key >> matchshift) == (T >> matchshift))
                atomicAdd(&sh[(key >> shift) & bmask], 1);
        } else {
            if (key == T && (((unsigned)i) >> matchshift) == (I >> matchshift))
                atomicAdd(&sh[(((unsigned)i) >> shift) & bmask], 1);
        }
    }
    __syncthreads();
    for (int j = threadIdx.x; j < 1024; j += 256)
        if (sh[j]) atomicAdd(&hist[j], sh[j]);
    __threadfence();
    if (threadIdx.x == 0) {
        unsigned d = atomicAdd(&g_done, 1u);
        slast = (d == gridDim.x - 1) ? 1 : 0;
    }
    __syncthreads();
    if (slast) {
        if (threadIdx.x == 0) g_done = 0;   // self-reset for next level / replay
        dev_pick(hist, bmask + 1, shift, kind);
    }
}

// selection + in-chunk exclusive prefix + chunk totals
__global__ void k_sel() {
    __shared__ int wsum[8];
    int e = blockIdx.x * blockDim.x + threadIdx.x;
    unsigned T = g_T, I = g_I;
    int sflag = 0;
    if (e < S3_ && e < g_E) {
        unsigned key = g_yk[e];
        sflag = (key < T || (key == T && (unsigned)e <= I)) ? 1 : 0;
    }
    int tot;
    int excl = blk_prefix(sflag, wsum, &tot);
    if (e < S3_) { g_selflag[e] = sflag; g_selpre[e] = excl; }
    if (threadIdx.x == 0) g_chS[blockIdx.x] = tot;
}

// per-face category + deterministic in-chunk per-category rank + chunk totals
__global__ void k_cat() {
    __shared__ int wcnt[8*8];    // [warp][cat]
    int fc = blockIdx.x * blockDim.x + threadIdx.x;
    int lane = threadIdx.x & 31, w = threadIdx.x >> 5;
    int cat = 8;                 // invalid for out-of-range threads
    if (fc < FN_) {
        int m0 = g_selflag[g_inv[fc]];
        int m1 = g_selflag[g_inv[FN_ + fc]];
        int m2 = g_selflag[g_inv[2*FN_ + fc]];
        int pen = m0 + m1 + m2;
        int psi = m1 + 2*m2;
        cat = (pen == 0) ? 0 : (pen == 1) ? 1 + psi : (pen == 2) ? 3 + psi : 7;
    }
    int rank_w = 0;
    #pragma unroll
    for (int c = 0; c < 8; c++) {
        unsigned m = __ballot_sync(0xFFFFFFFFu, cat == c);
        if (lane == 0) wcnt[w*8 + c] = __popc(m);
        if (cat == c) rank_w = __popc(m & ((1u << lane) - 1u));
    }
    __syncthreads();
    if (fc < FN_) {
        int off = 0;
        for (int j = 0; j < w; j++) off += wcnt[j*8 + cat];
        g_catpre[fc] = off + rank_w;
    }
    if (threadIdx.x < 8) {
        int c = threadIdx.x, tot = 0;
        #pragma unroll
        for (int j = 0; j < 8; j++) tot += wcnt[j*8 + c];
        g_chC[c*NCHF + blockIdx.x] = tot;
    }
}

// single-block: scan sel chunk totals and cat-major chunk totals; category starts
__global__ void k_tiny2() {
    __shared__ int part[1024];
    int t = threadIdx.x;
    // A: sel chunks (1172, 2 per thread)
    int a0 = (2*t   < NCHS) ? g_chS[2*t]   : 0;
    int a1 = (2*t+1 < NCHS) ? g_chS[2*t+1] : 0;
    part[t] = a0 + a1;
    __syncthreads();
    for (int d = 1; d < 1024; d <<= 1) {
        int v = (t >= d) ? part[t-d] : 0;
        __syncthreads();
        part[t] += v;
        __syncthreads();
    }
    int base = t ? part[t-1] : 0;
    if (2*t   < NCHS) g_offS[2*t]   = base;
    if (2*t+1 < NCHS) g_offS[2*t+1] = base + a0;
    __syncthreads();
    // B: cat chunks (8*391 = 3128, 4 per thread)
    int b4[4]; int loc = 0;
    #pragma unroll
    for (int j = 0; j < 4; j++) {
        int idx = 4*t + j;
        b4[j] = (idx < 8*NCHF) ? g_chC[idx] : 0;
        loc += b4[j];
    }
    part[t] = loc;
    __syncthreads();
    for (int d = 1; d < 1024; d <<= 1) {
        int v = (t >= d) ? part[t-d] : 0;
        __syncthreads();
        part[t] += v;
        __syncthreads();
    }
    int base2 = t ? part[t-1] : 0;
    int run = base2;
    #pragma unroll
    for (int j = 0; j < 4; j++) {
        int idx = 4*t + j;
        if (idx < 8*NCHF) { g_offC[idx] = run; run += b4[j]; }
    }
    __syncthreads();
    if (t < 8) g_catStart[t] = g_offC[t*NCHF];
    if (t == 0) g_catStart[8] = FN_;
}

__device__ __forceinline__ void wtri(int row, int a, int b, int c) {
    g_nf[row*3+0] = a; g_nf[row*3+1] = b; g_nf[row*3+2] = c;
}

__global__ void k_faces(const int* __restrict__ face) {
    int fc = blockIdx.x * blockDim.x + threadIdx.x;
    if (fc >= FN_) return;
    int T0, C1, C2, T7; cat_counts(T0, C1, C2, T7);
    int f0 = face[fc*3+0], f1 = face[fc*3+1], f2 = face[fc*3+2];
    int e0 = g_inv[fc], e1 = g_inv[FN_+fc], e2 = g_inv[2*FN_+fc];
    int m0 = g_selflag[e0], m1 = g_selflag[e1], m2 = g_selflag[e2];
    int p0 = VN_ + g_offS[e0>>8] + g_selpre[e0];
    int p1 = VN_ + g_offS[e1>>8] + g_selpre[e1];
    int p2 = VN_ + g_offS[e2>>8] + g_selpre[e2];
    int pen = m0 + m1 + m2, psi = m1 + 2*m2;
    int cat = (pen == 0) ? 0 : (pen == 1) ? 1 + psi : (pen == 2) ? 3 + psi : 7;
    // GLOBAL cumulative position: catStart[cat] + rank-within-cat.
    // (offC is the cat-major exclusive scan, so NO catStart subtraction —
    //  the downstream group-row mapping needs the cumulative base. This was
    //  the R8/R13 bug.)
    int pos = g_offC[cat*NCHF + blockIdx.x] + g_catpre[fc];
    if (cat == 0) {
        wtri(pos, f0, f1, f2);
    } else if (cat <= 3) {                  // pen==1
        int g = pos - T0;
        int rA = T0 + g, rB = T0 + C1 + g;
        if (cat == 1)      { wtri(rA, f0, p0, f2); wtri(rB, p0, f1, f2); }
        else if (cat == 2) { wtri(rA, f1, p1, f0); wtri(rB, p1, f2, f0); }
        else               { wtri(rA, f2, p2, f1); wtri(rB, p2, f0, f1); }
    } else if (cat <= 6) {                  // pen==2
        int g = pos - (T0 + C1);
        int base2 = T0 + 2*C1;
        int rA = base2 + g, rB = base2 + C2 + g, rC = base2 + 2*C2 + g;
        if (cat == 4)      { wtri(rA, f0, p0, f2); wtri(rB, p0, f1, p1); wtri(rC, p0, p1, f2); }
        else if (cat == 5) { wtri(rA, f2, p2, f1); wtri(rB, p2, f0, p0); wtri(rC, p2, p0, f1); }
        else               { wtri(rA, f1, p1, f0); wtri(rB, p1, f2, p2); wtri(rC, p1, p2, f0); }
    } else {                                // pen==3
        int r = pos - (T0 + C1 + C2);
        int base3 = T0 + 2*C1 + 3*C2;
        wtri(base3 + r,        f0, p0, p2);
        wtri(base3 + T7 + r,   p0, f1, p1);
        wtri(base3 + 2*T7 + r, p0, p1, p2);
        wtri(base3 + 3*T7 + r, p1, f2, p2);
    }
}

// all three output sections in one launch (block-range dispatch)
__global__ void k_outputs(float* __restrict__ out) {
    int b = blockIdx.x;
    if (b < GS3) {
        int e = b * TPB + threadIdx.x;
        if (e >= EMAX_ || e >= g_E) return;
        int NF = nf_total();
        int NE = VN_ + g_num + 3*NF;
        int oM = 2*g_E + 3*NF + 2*NE;
        out[2*e]   = (float)g_en0[e];
        out[2*e+1] = (float)g_en1[e];
        float y  = g_y[e];
        float yh = g_selflag[e] ? 1.f : 0.f;
        out[oM + e] = (yh - y) + y;      // straight-through mask
    } else if (b < GS3 + GNF3) {
        int i = (b - GS3) * TPB + threadIdx.x;
        if (i >= 3*NFMAX_ || i >= 3*nf_total()) return;
        out[2*g_E + i] = (float)g_nf[i];
    } else {
        int t = (b - GS3 - GNF3) * TPB + threadIdx.x;
        if (t >= NEM_) return;
        int NF = nf_total();
        int NE = VN_ + g_num + 3*NF;
        if (t >= NE) return;
        int oNE = 2*g_E + 3*NF;
        int base = VN_ + g_num;
        int s, d;
        if (t < base) { s = t; d = t; }
        else {
            int u = t - base;
            if (u < NF)          { s = g_nf[u*3+0];        d = g_nf[u*3+1]; }
            else if (u < 2*NF)   { int r = u - NF;   s = g_nf[r*3+1]; d = g_nf[r*3+2]; }
            else                 { int r = u - 2*NF; s = g_nf[r*3+2]; d = g_nf[r*3+0]; }
        }
        out[oNE + t]      = (float)s;
        out[oNE + NE + t] = (float)d;
    }
}

// ---------------- host ----------------
extern "C" void kernel_launch(void* const* d_in, const int* in_sizes, int n_in,
                              void* d_out, int out_size) {
    const float* x    = (const float*)d_in[0];
    const int*   face = (const int*)d_in[1];
    const int*   divp = (const int*)d_in[4];
    const float* W1s  = (const float*)d_in[5];
    const float* W1n  = (const float*)d_in[6];
    const float* b1   = (const float*)d_in[7];
    const float* W2s  = (const float*)d_in[8];
    const float* W2n  = (const float*)d_in[9];
    const float* b2   = (const float*)d_in[10];
    float* out = (float*)d_out;

    void *tp, *psk_in, *psk_out, *psv_in, *psv_out, *phistK, *phistI;
    cudaGetSymbolAddress(&tp,      g_temp);
    cudaGetSymbolAddress(&psk_in,  g_sk_in);
    cudaGetSymbolAddress(&psk_out, g_sk_out);
    cudaGetSymbolAddress(&psv_in,  g_sv_in);
    cudaGetSymbolAddress(&psv_out, g_sv_out);
    cudaGetSymbolAddress(&phistK,  g_histK);
    cudaGetSymbolAddress(&phistI,  g_histI);
    cudaStream_t st = 0;
    size_t tb;

    k_build_keys<<<GS3, TPB, 0, st>>>(face);

    tb = sizeof(g_temp);
    cub::DeviceRadixSort::SortPairs(tp, tb,
        (const unsigned*)psk_in, (unsigned*)psk_out,
        (const unsigned*)psv_in, (unsigned*)psv_out, S3_, 0, 32, st);

    k_head<<<GS3, TPB, 0, st>>>();
    k_tiny1<<<1, 1024, 0, st>>>();
    k_unique<<<GS3, TPB, 0, st>>>(x, divp);
    k_gnn1<<<GS3, TPB, 0, st>>>(W1s, W1n, b1, W2s, W2n);
    k_gumbel<<<GS3, TPB, 0, st>>>(b2);

    // radix-select: key 3x10 bits, tie-index 10+9 bits; pick fused into each level
    k_histpick<<<GS3, TPB, 0, st>>>(20, 30, 1023, 0, 0, (int*)phistK);
    k_histpick<<<GS3, TPB, 0, st>>>(10, 20, 1023, 1, 0, (int*)phistK);
    k_histpick<<<GS3, TPB, 0, st>>>( 0, 10, 1023, 1, 0, (int*)phistK);
    k_histpick<<<GS3, TPB, 0, st>>>( 9, 19, 1023, 2, 1, (int*)phistI);
    k_histpick<<<GS3, TPB, 0, st>>>( 0,  9,  511, 3, 1, (int*)phistI);

    k_sel<<<GS3, TPB, 0, st>>>();
    k_cat<<<GF, TPB, 0, st>>>();
    k_tiny2<<<1, 1024, 0, st>>>();
    k_faces<<<GF, TPB, 0, st>>>(face);

    k_outputs<<<GS3 + GNF3 + GNE, TPB, 0, st>>>(out);
}

// round 15
// speedup vs baseline: 2.0227x; 1.0911x over previous
#include <cuda_runtime.h>
#include <cstdint>
#include <cub/cub.cuh>

#define VN_    50000
#define FN_    100000
#define S3_    (3*FN_)
#define EMAX_  S3_
#define HID_   256
#define NFMAX_ (4*FN_)
#define PEMAX_ ((S3_/5)+64)
#define NEM_   (VN_ + PEMAX_ + 3*NFMAX_)
#define SF_    (S3_ + 8*FN_)          // combined sel+flag8 scan length
#define TPB    256
#define GS3    ((S3_ + TPB - 1)/TPB)  // 1172
#define GF     ((FN_ + TPB - 1)/TPB)
#define GNE    ((NEM_ + TPB - 1)/TPB)
#define GNF3   ((3*NFMAX_ + TPB - 1)/TPB)
#define NCHS   GS3
#define NBSEL  148

// ---------------- static device scratch (no allocation allowed) ----------------
__device__ unsigned g_sk_in[S3_], g_sk_out[S3_], g_sv_in[S3_], g_sv_out[S3_];
__device__ int g_rank[S3_], g_inv[S3_];
__device__ int g_chU[NCHS], g_offU[NCHS];
__device__ int g_runstart[EMAX_+1];
__device__ int g_en0[EMAX_], g_en1[EMAX_];
__device__ float g_xe[EMAX_*4];      // padded to 4 floats/edge for vector loads
__device__ float g_rq[EMAX_*4];      // r0,r1,q0,q1 per edge (float4)
__device__ float g_y[EMAX_];
__device__ unsigned g_yk[S3_];       // 30-bit selection keys (~float_bits(y))
__device__ int g_selflag[SF_];       // [0,S3_): sel ; [S3_,S3_+8FN): flag8
__device__ int g_scan[SF_];          // exclusive scan of g_selflag
__device__ int g_nf[3*NFMAX_];
__device__ int g_histK[1024];        // key-select histogram (picks re-zero)
__device__ int g_histI[1024];        // index-select histogram (picks re-zero)
__device__ unsigned g_T;             // threshold key (30-bit)
__device__ int g_RK;                 // remaining count within key threshold
__device__ unsigned g_I;             // tie threshold index I* (19-bit)
__device__ int g_RI;
__device__ unsigned g_arrive = 0, g_gen = 0;   // grid barrier (replay-safe)
__device__ int g_E, g_num;
__device__ unsigned char g_temp[48u<<20];

// ---------------- threefry2x32, key = (0,42), JAX-exact ----------------
__device__ __forceinline__ unsigned rotl32(unsigned v, int d) {
    return (v << d) | (v >> (32 - d));
}
__device__ __forceinline__ void threefry_0_42(unsigned x0, unsigned x1,
                                              unsigned& o0, unsigned& o1) {
    const unsigned k0 = 0u, k1 = 42u;
    const unsigned ks2 = k0 ^ k1 ^ 0x1BD11BDAu;
    x0 += k0; x1 += k1;
#define TF4(a,b,c,d) \
    x0 += x1; x1 = rotl32(x1,a); x1 ^= x0; \
    x0 += x1; x1 = rotl32(x1,b); x1 ^= x0; \
    x0 += x1; x1 = rotl32(x1,c); x1 ^= x0; \
    x0 += x1; x1 = rotl32(x1,d); x1 ^= x0;
    TF4(13,15,26,6);   x0 += k1;  x1 += ks2 + 1u;
    TF4(17,29,16,24);  x0 += ks2; x1 += k0  + 2u;
    TF4(13,15,26,6);   x0 += k0;  x1 += k1  + 3u;
    TF4(17,29,16,24);  x0 += k1;  x1 += ks2 + 4u;
    TF4(13,15,26,6);   x0 += ks2; x1 += k0  + 5u;
#undef TF4
    o0 = x0; o1 = x1;
}
// Partitionable-threefry (JAX >= 0.5 default): bits[i] = xor(threefry((0,42),(0,i)))
__device__ __forceinline__ unsigned tf_bits_part(unsigned i) {
    unsigned o0, o1;
    threefry_0_42(0u, i, o0, o1);
    return o0 ^ o1;
}

// exclusive in-block binary prefix over 256 threads; also returns block total
__device__ __forceinline__ int blk_prefix(int flag, int* wsum, int* total) {
    unsigned m = __ballot_sync(0xFFFFFFFFu, flag != 0);
    int lane = threadIdx.x & 31, w = threadIdx.x >> 5;
    int excl = __popc(m & ((1u << lane) - 1u));
    if (lane == 0) wsum[w] = __popc(m);
    __syncthreads();
    int off = 0, tot = 0;
    #pragma unroll
    for (int j = 0; j < 8; j++) { int v = wsum[j]; tot += v; if (j < w) off += v; }
    *total = tot;
    __syncthreads();
    return excl + off;
}

// derived category counts from the combined scan (R10-proven)
__device__ __forceinline__ void cat_counts(int& T0, int& C1, int& C2, int& T7) {
    int num = g_num;
    int P1 = g_scan[S3_ +   FN_] - num;
    int P4 = g_scan[S3_ + 4*FN_] - num;
    int P7 = g_scan[S3_ + 7*FN_] - num;
    T0 = P1; C1 = P4 - P1; C2 = P7 - P4; T7 = FN_ - P7;
}
__device__ __forceinline__ int nf_total() {
    int T0, C1, C2, T7; cat_counts(T0, C1, C2, T7);
    return T0 + 2*C1 + 3*C2 + 4*T7;
}

// ---------------- kernels ----------------
__global__ void k_build_keys(const int* __restrict__ face) {
    int i = blockIdx.x * blockDim.x + threadIdx.x;
    if (i >= S3_) return;
    int blk = i / FN_, fc = i - blk * FN_;
    int a, b;
    if (blk == 0)      { a = face[fc*3+0]; b = face[fc*3+1]; }
    else if (blk == 1) { a = face[fc*3+1]; b = face[fc*3+2]; }
    else               { a = face[fc*3+2]; b = face[fc*3+0]; }
    int lo = min(a, b), hi = max(a, b);
    int key = (int)((unsigned)lo * (unsigned)VN_ + (unsigned)hi); // int32 wrap like JAX
    g_sk_in[i] = (unsigned)key ^ 0x80000000u;  // signed order under unsigned radix
    g_sv_in[i] = (unsigned)i;
}

// head flags + in-chunk inclusive prefix + chunk totals (proven since R9)
__global__ void k_head() {
    __shared__ int wsum[8];
    int i = blockIdx.x * blockDim.x + threadIdx.x;
    int flag = (i < S3_) && (i == 0 || g_sk_out[i] != g_sk_out[i-1]);
    int tot;
    int excl = blk_prefix(flag, wsum, &tot);
    if (i < S3_) g_rank[i] = excl + flag;   // in-chunk inclusive
    if (threadIdx.x == 0) g_chU[blockIdx.x] = tot;
}

// single-block exclusive scan of chunk totals
__global__ void k_tiny1() {
    __shared__ int part[1024];
    int t = threadIdx.x;
    int a0 = (2*t   < NCHS) ? g_chU[2*t]   : 0;
    int a1 = (2*t+1 < NCHS) ? g_chU[2*t+1] : 0;
    part[t] = a0 + a1;
    __syncthreads();
    for (int d = 1; d < 1024; d <<= 1) {
        int v = (t >= d) ? part[t-d] : 0;
        __syncthreads();
        part[t] += v;
        __syncthreads();
    }
    int base = t ? part[t-1] : 0;
    if (2*t   < NCHS) g_offU[2*t]   = base;
    if (2*t+1 < NCHS) g_offU[2*t+1] = base + a0;
}

// unique + inverse map + scalars + edge-node endpoints + xe, fused
__global__ void k_unique(const float* __restrict__ x, const int* __restrict__ divp) {
    int i = blockIdx.x * blockDim.x + threadIdx.x;
    if (i >= S3_) return;
    int r = g_offU[blockIdx.x] + g_rank[i];   // global inclusive rank
    int flag = (i == 0 || g_sk_out[i] != g_sk_out[i-1]);
    if (flag) {
        int e = r - 1;
        g_runstart[e] = i;
        int k = (int)(g_sk_out[i] ^ 0x80000000u);
        int q = k / VN_, rm = k % VN_;     // C trunc -> numpy floor fixup
        if (rm < 0) { rm += VN_; q -= 1; }
        g_en0[e] = q; g_en1[e] = rm;
        int i0 = (q < 0) ? q + VN_ : q;    // JAX gather: negative wrap, then clamp
        if (i0 < 0) i0 = 0;
        if (i0 >= VN_) i0 = VN_ - 1;
        float4 v;
        v.x = 0.5f * (x[i0*3+0] + x[rm*3+0]);
        v.y = 0.5f * (x[i0*3+1] + x[rm*3+1]);
        v.z = 0.5f * (x[i0*3+2] + x[rm*3+2]);
        v.w = 0.f;
        *(float4*)&g_xe[e*4] = v;
    }
    g_inv[g_sv_out[i]] = r - 1;
    if (i == S3_ - 1) { g_E = r; g_runstart[r] = S3_; g_num = r / divp[0]; }
}

__global__ void k_gnn1(const float* __restrict__ W1s, const float* __restrict__ W1n,
                       const float* __restrict__ b1,  const float* __restrict__ W2s,
                       const float* __restrict__ W2n) {
    __shared__ float s1s[3*HID_], s1n[3*HID_], sb[HID_], s2s[2*HID_], s2n[2*HID_];
    for (int i = threadIdx.x; i < 3*HID_; i += blockDim.x) { s1s[i] = W1s[i]; s1n[i] = W1n[i]; }
    for (int i = threadIdx.x; i < HID_;   i += blockDim.x) {
        sb[i] = b1[i];
        s2s[i] = W2s[i*2+0]; s2s[HID_+i] = W2s[i*2+1];
        s2n[i] = W2n[i*2+0]; s2n[HID_+i] = W2n[i*2+1];
    }
    __syncthreads();
    int e = blockIdx.x * blockDim.x + threadIdx.x;
    if (e >= EMAX_ || e >= g_E) return;
    int s = g_runstart[e], t = g_runstart[e+1];
    float deg = (float)(2*(t-s) + 1);
    float4 xev = *(const float4*)&g_xe[e*4];
    float xe0 = xev.x, xe1 = xev.y, xe2 = xev.z;
    float ax0 = xe0, ax1 = xe1, ax2 = xe2;   // self loop
    for (int i = s; i < t; i++) {
        int slot = (int)g_sv_out[i];
        int fc = slot % FN_, j = slot / FN_;
        int e1 = g_inv[((j+1)%3)*FN_ + fc];
        int e2 = g_inv[((j+2)%3)*FN_ + fc];
        float4 v1 = *(const float4*)&g_xe[e1*4];
        float4 v2 = *(const float4*)&g_xe[e2*4];
        ax0 += v1.x + v2.x;
        ax1 += v1.y + v2.y;
        ax2 += v1.z + v2.z;
    }
    ax0 /= deg; ax1 /= deg; ax2 /= deg;
    float r0 = 0.f, r1 = 0.f, q0 = 0.f, q1 = 0.f;
    for (int k4 = 0; k4 < HID_; k4 += 4) {
        float4 vb  = *(const float4*)&sb[k4];
        float4 a0v = *(const float4*)&s1s[k4];
        float4 a1v = *(const float4*)&s1s[HID_ + k4];
        float4 a2v = *(const float4*)&s1s[2*HID_ + k4];
        float4 n0v = *(const float4*)&s1n[k4];
        float4 n1v = *(const float4*)&s1n[HID_ + k4];
        float4 n2v = *(const float4*)&s1n[2*HID_ + k4];
        float4 w0v = *(const float4*)&s2s[k4];
        float4 w1v = *(const float4*)&s2s[HID_ + k4];
        float4 u0v = *(const float4*)&s2n[k4];
        float4 u1v = *(const float4*)&s2n[HID_ + k4];
        #define GNN_STEP(c) { \
            float pre = vb.c + xe0*a0v.c + xe1*a1v.c + xe2*a2v.c \
                             + ax0*n0v.c + ax1*n1v.c + ax2*n2v.c; \
            float h = fmaxf(pre, 0.f); \
            r0 += h * w0v.c;  r1 += h * w1v.c; \
            q0 += h * u0v.c;  q1 += h * u1v.c; }
        GNN_STEP(x) GNN_STEP(y) GNN_STEP(z) GNN_STEP(w)
        #undef GNN_STEP
    }
    float4 outv; outv.x = r0; outv.y = r1; outv.z = q0; outv.w = q1;
    *(float4*)&g_rq[e*4] = outv;
}

__global__ void k_gumbel(const float* __restrict__ b2) {
    int e = blockIdx.x * blockDim.x + threadIdx.x;
    if (e >= S3_) return;
    int E = g_E;
    if (e >= E) { g_yk[e] = 0xFFFFFFFFu; return; }
    int s = g_runstart[e], t = g_runstart[e+1];
    float deg = (float)(2*(t-s) + 1);
    float4 rqv = *(const float4*)&g_rq[e*4];
    float aq0 = rqv.z, aq1 = rqv.w;              // self loop
    for (int i = s; i < t; i++) {
        int slot = (int)g_sv_out[i];
        int fc = slot % FN_, j = slot / FN_;
        int e1 = g_inv[((j+1)%3)*FN_ + fc];
        int e2 = g_inv[((j+2)%3)*FN_ + fc];
        float4 v1 = *(const float4*)&g_rq[e1*4];
        float4 v2 = *(const float4*)&g_rq[e2*4];
        aq0 += v1.z + v2.z;
        aq1 += v1.w + v2.w;
    }
    float o0 = rqv.x + aq0/deg + b2[0];
    float o1 = rqv.y + aq1/deg + b2[1];
    float l0 = 1.f / (1.f + expf(-o0));           // sigmoid logits
    float l1 = 1.f / (1.f + expf(-o1));
    unsigned bb0 = tf_bits_part(2u*(unsigned)e);
    unsigned bb1 = tf_bits_part(2u*(unsigned)e + 1u);
    float U0 = __uint_as_float((bb0 >> 9) | 0x3F800000u) - 1.0f;
    float U1 = __uint_as_float((bb1 >> 9) | 0x3F800000u) - 1.0f;
    float gg0 = -logf(-logf(U0 + 1e-20f) + 1e-20f);
    float gg1 = -logf(-logf(U1 + 1e-20f) + 1e-20f);
    float z0 = (l0 + gg0) / 0.1f, z1 = (l1 + gg1) / 0.1f;
    float m  = fmaxf(z0, z1);
    float ez0 = expf(z0 - m), ez1 = expf(z1 - m);
    float y = ez0 / (ez0 + ez1);
    g_y[e] = y;
    g_yk[e] = (~__float_as_uint(y)) & 0x3FFFFFFFu;  // smaller key == larger y
}

// ---- replay-safe grid barrier (generation counter; arrive self-resets) ----
__device__ __forceinline__ void gridsync(int nb) {
    __syncthreads();
    if (threadIdx.x == 0) {
        __threadfence();
        unsigned gen = *((volatile unsigned*)&g_gen);
        if (atomicAdd(&g_arrive, 1u) == (unsigned)(nb - 1)) {
            g_arrive = 0;
            __threadfence();
            atomicAdd(&g_gen, 1u);
        } else {
            while (*((volatile unsigned*)&g_gen) == gen) __nanosleep(64);
        }
        __threadfence();
    }
    __syncthreads();
}

// pick (whole block 0): find k-th crossing, update state, re-zero hist
__device__ void dev_pick(int* hist, int nb, int shift, int kind) {
    __shared__ int sc[256];
    int t = threadIdx.x;
    int per = nb >> 8;
    int base = t * per;
    int vals[4];
    int local = 0;
    for (int j = 0; j < per; j++) { vals[j] = hist[base+j]; hist[base+j] = 0; local += vals[j]; }
    sc[t] = local;
    __syncthreads();
    for (int d = 1; d < 256; d <<= 1) {
        int v = (t >= d) ? sc[t-d] : 0;
        __syncthreads();
        sc[t] += v;
        __syncthreads();
    }
    int k = (kind == 0) ? g_num : (kind == 3) ? g_RI : g_RK;
    int cumex = sc[t] - local;
    if (cumex < k && sc[t] >= k) {
        int c = cumex;
        for (int j = 0; j < per; j++) {
            if (c + vals[j] >= k) {
                unsigned b = (unsigned)(base + j);
                int rem = k - c;
                if (kind == 0)      { g_T = b << shift; g_RK = rem; }
                else if (kind == 1) { g_T |= b << shift; g_RK = rem; }
                else if (kind == 2) { g_I = b << shift; g_RI = rem; }
                else                { g_I |= b << shift; }
                break;
            }
            c += vals[j];
        }
    }
    __syncthreads();
}

// ONE persistent kernel: 5-level radix-select (key 3x10b, tie-index 10+9b)
// then the final selection flag write. 148 blocks = 1/SM, co-resident.
__global__ void __launch_bounds__(256) k_select() {
    __shared__ int sh[1024];
    const int nb = NBSEL;
    const int tid = threadIdx.x, bid = blockIdx.x;
    const int stride = nb * 256;
    int E = g_E;

    #pragma unroll
    for (int lvl = 0; lvl < 5; lvl++) {
        int shift, matchshift, bmask, kind; int* hist; bool idxlevel;
        if (lvl == 0)      { shift = 20; matchshift = 30; bmask = 1023; kind = 0; hist = g_histK; idxlevel = false; }
        else if (lvl == 1) { shift = 10; matchshift = 20; bmask = 1023; kind = 1; hist = g_histK; idxlevel = false; }
        else if (lvl == 2) { shift =  0; matchshift = 10; bmask = 1023; kind = 1; hist = g_histK; idxlevel = false; }
        else if (lvl == 3) { shift =  9; matchshift = 19; bmask = 1023; kind = 2; hist = g_histI; idxlevel = true;  }
        else               { shift =  0; matchshift =  9; bmask =  511; kind = 3; hist = g_histI; idxlevel = true;  }

        for (int j = tid; j < 1024; j += 256) sh[j] = 0;
        __syncthreads();
        unsigned T = g_T, I = g_I;   // stale at lvl 0 is fine: matchshift=30 vs top bits 0
        for (int i = bid * 256 + tid; i < E; i += stride) {
            unsigned key = g_yk[i];
            if (!idxlevel) {
                if ((key >> matchshift) == (T >> matchshift))
                    atomicAdd(&sh[(key >> shift) & bmask], 1);
            } else {
                if (key == T && (((unsigned)i) >> matchshift) == (I >> matchshift))
                    atomicAdd(&sh[(((unsigned)i) >> shift) & bmask], 1);
            }
        }
        __syncthreads();
        for (int j = tid; j < 1024; j += 256)
            if (sh[j]) atomicAdd(&hist[j], sh[j]);
        gridsync(nb);
        if (bid == 0) dev_pick(hist, bmask + 1, shift, kind);
        gridsync(nb);
    }

    // final selection flags (grid-stride; 0 for padding beyond E)
    unsigned T = g_T, I = g_I;
    for (int e = bid * 256 + tid; e < S3_; e += stride) {
        int s = 0;
        if (e < E) {
            unsigned key = g_yk[e];
            s = (key < T || (key == T && (unsigned)e <= I)) ? 1 : 0;
        }
        g_selflag[e] = s;
    }
}

__global__ void k_cat() {
    int fc = blockIdx.x * blockDim.x + threadIdx.x;
    if (fc >= FN_) return;
    int m0 = g_selflag[g_inv[fc]];
    int m1 = g_selflag[g_inv[FN_ + fc]];
    int m2 = g_selflag[g_inv[2*FN_ + fc]];
    int pen = m0 + m1 + m2;
    int psi = m1 + 2*m2;
    int cat = (pen == 0) ? 0 : (pen == 1) ? 1 + psi : (pen == 2) ? 3 + psi : 7;
    #pragma unroll
    for (int k = 0; k < 8; k++) g_selflag[S3_ + k*FN_ + fc] = (k == cat) ? 1 : 0;
}

__device__ __forceinline__ void wtri(int row, int a, int b, int c) {
    g_nf[row*3+0] = a; g_nf[row*3+1] = b; g_nf[row*3+2] = c;
}

__global__ void k_faces(const int* __restrict__ face) {
    int fc = blockIdx.x * blockDim.x + threadIdx.x;
    if (fc >= FN_) return;
    int T0, C1, C2, T7; cat_counts(T0, C1, C2, T7);
    int num = g_num;
    int f0 = face[fc*3+0], f1 = face[fc*3+1], f2 = face[fc*3+2];
    int e0 = g_inv[fc], e1 = g_inv[FN_+fc], e2 = g_inv[2*FN_+fc];
    int m0 = g_selflag[e0], m1 = g_selflag[e1], m2 = g_selflag[e2];
    int p0 = VN_ + g_scan[e0], p1 = VN_ + g_scan[e1], p2 = VN_ + g_scan[e2];
    int pen = m0 + m1 + m2, psi = m1 + 2*m2;
    int cat = (pen == 0) ? 0 : (pen == 1) ? 1 + psi : (pen == 2) ? 3 + psi : 7;
    int pos = g_scan[S3_ + cat*FN_ + fc] - num;   // global cumulative position
    if (cat == 0) {
        wtri(pos, f0, f1, f2);
    } else if (cat <= 3) {                  // pen==1
        int g = pos - T0;
        int rA = T0 + g, rB = T0 + C1 + g;
        if (cat == 1)      { wtri(rA, f0, p0, f2); wtri(rB, p0, f1, f2); }
        else if (cat == 2) { wtri(rA, f1, p1, f0); wtri(rB, p1, f2, f0); }
        else               { wtri(rA, f2, p2, f1); wtri(rB, p2, f0, f1); }
    } else if (cat <= 6) {                  // pen==2
        int g = pos - (T0 + C1);
        int base2 = T0 + 2*C1;
        int rA = base2 + g, rB = base2 + C2 + g, rC = base2 + 2*C2 + g;
        if (cat == 4)      { wtri(rA, f0, p0, f2); wtri(rB, p0, f1, p1); wtri(rC, p0, p1, f2); }
        else if (cat == 5) { wtri(rA, f2, p2, f1); wtri(rB, p2, f0, p0); wtri(rC, p2, p0, f1); }
        else               { wtri(rA, f1, p1, f0); wtri(rB, p1, f2, p2); wtri(rC, p1, p2, f0); }
    } else {                                // pen==3
        int r = pos - (T0 + C1 + C2);
        int base3 = T0 + 2*C1 + 3*C2;
        wtri(base3 + r,        f0, p0, p2);
        wtri(base3 + T7 + r,   p0, f1, p1);
        wtri(base3 + 2*T7 + r, p0, p1, p2);
        wtri(base3 + 3*T7 + r, p1, f2, p2);
    }
}

// all three output sections in one launch (block-range dispatch)
__global__ void k_outputs(float* __restrict__ out) {
    int b = blockIdx.x;
    if (b < GS3) {
        int e = b * TPB + threadIdx.x;
        if (e >= EMAX_ || e >= g_E) return;
        int NF = nf_total();
        int NE = VN_ + g_num + 3*NF;
        int oM = 2*g_E + 3*NF + 2*NE;
        out[2*e]   = (float)g_en0[e];
        out[2*e+1] = (float)g_en1[e];
        float y  = g_y[e];
        float yh = g_selflag[e] ? 1.f : 0.f;
        out[oM + e] = (yh - y) + y;      // straight-through mask
    } else if (b < GS3 + GNF3) {
        int i = (b - GS3) * TPB + threadIdx.x;
        if (i >= 3*NFMAX_ || i >= 3*nf_total()) return;
        out[2*g_E + i] = (float)g_nf[i];
    } else {
        int t = (b - GS3 - GNF3) * TPB + threadIdx.x;
        if (t >= NEM_) return;
        int NF = nf_total();
        int NE = VN_ + g_num + 3*NF;
        if (t >= NE) return;
        int oNE = 2*g_E + 3*NF;
        int base = VN_ + g_num;
        int s, d;
        if (t < base) { s = t; d = t; }
        else {
            int u = t - base;
            if (u < NF)          { s = g_nf[u*3+0];        d = g_nf[u*3+1]; }
            else if (u < 2*NF)   { int r = u - NF;   s = g_nf[r*3+1]; d = g_nf[r*3+2]; }
            else                 { int r = u - 2*NF; s = g_nf[r*3+2]; d = g_nf[r*3+0]; }
        }
        out[oNE + t]      = (float)s;
        out[oNE + NE + t] = (float)d;
    }
}

// ---------------- host ----------------
extern "C" void kernel_launch(void* const* d_in, const int* in_sizes, int n_in,
                              void* d_out, int out_size) {
    const float* x    = (const float*)d_in[0];
    const int*   face = (const int*)d_in[1];
    const int*   divp = (const int*)d_in[4];
    const float* W1s  = (const float*)d_in[5];
    const float* W1n  = (const float*)d_in[6];
    const float* b1   = (const float*)d_in[7];
    const float* W2s  = (const float*)d_in[8];
    const float* W2n  = (const float*)d_in[9];
    const float* b2   = (const float*)d_in[10];
    float* out = (float*)d_out;

    void *tp, *psk_in, *psk_out, *psv_in, *psv_out, *pselflag, *pscan;
    cudaGetSymbolAddress(&tp,      g_temp);
    cudaGetSymbolAddress(&psk_in,  g_sk_in);
    cudaGetSymbolAddress(&psk_out, g_sk_out);
    cudaGetSymbolAddress(&psv_in,  g_sv_in);
    cudaGetSymbolAddress(&psv_out, g_sv_out);
    cudaGetSymbolAddress(&pselflag,g_selflag);
    cudaGetSymbolAddress(&pscan,   g_scan);
    cudaStream_t st = 0;
    size_t tb;

    k_build_keys<<<GS3, TPB, 0, st>>>(face);

    tb = sizeof(g_temp);
    cub::DeviceRadixSort::SortPairs(tp, tb,
        (const unsigned*)psk_in, (unsigned*)psk_out,
        (const unsigned*)psv_in, (unsigned*)psv_out, S3_, 0, 32, st);

    k_head<<<GS3, TPB, 0, st>>>();
    k_tiny1<<<1, 1024, 0, st>>>();
    k_unique<<<GS3, TPB, 0, st>>>(x, divp);
    k_gnn1<<<GS3, TPB, 0, st>>>(W1s, W1n, b1, W2s, W2n);
    k_gumbel<<<GS3, TPB, 0, st>>>(b2);

    // fused 5-level radix-select + selection flags, one persistent launch
    k_select<<<NBSEL, 256, 0, st>>>();

    k_cat<<<GF, TPB, 0, st>>>();
    // one combined scan: sel (pool ranks) + 8-category face flags (R10-proven)
    tb = sizeof(g_temp);
    cub::DeviceScan::ExclusiveSum(tp, tb, (const int*)pselflag, (int*)pscan, SF_, st);
    k_faces<<<GF, TPB, 0, st>>>(face);

    k_outputs<<<GS3 + GNF3 + GNE, TPB, 0, st>>>(out);
}